// round 6
// baseline (speedup 1.0000x reference)
#include <cuda_runtime.h>

// TemperatureScaler: piecewise-linear temperature scaling of logits.
// out = T[b]*x + C[b],  b = searchsorted(sorted_thr, x, 'left').
// Fast path: thresholds form a uniform grid (linspace) ->
//   b = clamp(ceil(fma(x, inv_s, k)), 0, 7),  k = -thr0/s.

#define TS_TEMP_MIN 1e-4f

__device__ __forceinline__ void ts_build_params(
    const float* __restrict__ temperature, const float* __restrict__ thresholds,
    float* th /*7 sorted*/, float* T /*8*/, float* C /*8*/)
{
    #pragma unroll
    for (int i = 0; i < 7; i++) th[i] = thresholds[i];
    // insertion sort (7 elements) == jnp.sort
    #pragma unroll
    for (int i = 1; i < 7; i++) {
        float v = th[i];
        int j = i - 1;
        while (j >= 0 && th[j] > v) { th[j + 1] = th[j]; j--; }
        th[j + 1] = v;
    }
    #pragma unroll
    for (int i = 0; i < 8; i++) {
        float t = temperature[i];
        T[i] = t < TS_TEMP_MIN ? TS_TEMP_MIN : t;   // clip(lo=1e-4)
    }
    float thrp[8];
    thrp[0] = 0.0f;
    #pragma unroll
    for (int i = 0; i < 7; i++) thrp[i + 1] = th[i];
    // c = cumsum(diff(pad(thr, left0)) * T[:-1])
    float c[8];
    c[0] = 0.0f;
    #pragma unroll
    for (int i = 0; i < 7; i++) {
        float d = __fadd_rn(thrp[i + 1], -thrp[i]);
        c[i + 1] = __fadd_rn(c[i], __fmul_rn(d, T[i]));
    }
    // C[b] = c[b] - T[b]*thrp[b]  (single-FFMA form; ulp-level deviation only)
    #pragma unroll
    for (int i = 0; i < 8; i++) C[i] = __fmaf_rn(-T[i], thrp[i], c[i]);
}

__global__ __launch_bounds__(256) void ts_kernel(
    const float4* __restrict__ in, float4* __restrict__ out,
    const float* __restrict__ temperature, const float* __restrict__ thresholds,
    int n4)
{
    __shared__ float2 lut[8];   // (T, C)
    __shared__ float sthr[7];   // sorted thresholds (fallback path)
    __shared__ float s_inv, s_k;
    __shared__ int   s_uniform;

    if (threadIdx.x == 0) {
        float th[7], T[8], C[8];
        ts_build_params(temperature, thresholds, th, T, C);
        #pragma unroll
        for (int i = 0; i < 8; i++) lut[i] = make_float2(T[i], C[i]);
        #pragma unroll
        for (int i = 0; i < 7; i++) sthr[i] = th[i];
        // uniform-grid detection (exact fp equality required)
        float step = __fadd_rn(th[1], -th[0]);
        int uni = (step > 0.0f);
        #pragma unroll
        for (int i = 0; i < 7; i++) {
            if (th[i] != __fmaf_rn((float)i, step, th[0])) uni = 0;
        }
        float inv = (step > 0.0f) ? (1.0f / step) : 0.0f;
        s_inv = inv;
        s_k   = __fmul_rn(-th[0], inv);
        s_uniform = uni;
    }
    __syncthreads();

    const int base = blockIdx.x * 1024 + threadIdx.x;

    if (s_uniform) {
        const float inv = s_inv, k = s_k;
        auto piece = [&](float x) -> float {
            // b = clamp(ceil((x - thr0)/s), 0, 7); boundary rounding safe by continuity
            int b = __float2int_ru(__fmaf_rn(x, inv, k));
            b = b < 0 ? 0 : b;
            b = b > 7 ? 7 : b;
            float2 L = lut[b];
            return __fmaf_rn(L.x, x, L.y);
        };
        if (base + 768 < n4) {
            float4 v0 = in[base];
            float4 v1 = in[base + 256];
            float4 v2 = in[base + 512];
            float4 v3 = in[base + 768];
            float4 r0, r1, r2, r3;
            r0.x = piece(v0.x); r0.y = piece(v0.y); r0.z = piece(v0.z); r0.w = piece(v0.w);
            r1.x = piece(v1.x); r1.y = piece(v1.y); r1.z = piece(v1.z); r1.w = piece(v1.w);
            r2.x = piece(v2.x); r2.y = piece(v2.y); r2.z = piece(v2.z); r2.w = piece(v2.w);
            r3.x = piece(v3.x); r3.y = piece(v3.y); r3.z = piece(v3.z); r3.w = piece(v3.w);
            out[base]       = r0;
            out[base + 256] = r1;
            out[base + 512] = r2;
            out[base + 768] = r3;
        } else {
            #pragma unroll
            for (int kk = 0; kk < 4; kk++) {
                int i = base + kk * 256;
                if (i < n4) {
                    float4 v = in[i];
                    float4 r;
                    r.x = piece(v.x); r.y = piece(v.y); r.z = piece(v.z); r.w = piece(v.w);
                    out[i] = r;
                }
            }
        }
    } else {
        // generic fallback: compare-chain bin search
        const float t0 = sthr[0], t1 = sthr[1], t2 = sthr[2], t3 = sthr[3],
                    t4 = sthr[4], t5 = sthr[5], t6 = sthr[6];
        auto piece = [&](float x) -> float {
            int b = (x > t0);
            b += (x > t1); b += (x > t2); b += (x > t3);
            b += (x > t4); b += (x > t5); b += (x > t6);
            float2 L = lut[b];
            return __fmaf_rn(L.x, x, L.y);
        };
        #pragma unroll
        for (int kk = 0; kk < 4; kk++) {
            int i = base + kk * 256;
            if (i < n4) {
                float4 v = in[i];
                float4 r;
                r.x = piece(v.x); r.y = piece(v.y); r.z = piece(v.z); r.w = piece(v.w);
                out[i] = r;
            }
        }
    }
}

// Scalar tail for out_size % 4 != 0 (not hit for B=64, V=128000)
__global__ void ts_tail_kernel(
    const float* __restrict__ in, float* __restrict__ out,
    const float* __restrict__ temperature, const float* __restrict__ thresholds,
    int start, int n)
{
    float th[7], T[8], C[8];
    ts_build_params(temperature, thresholds, th, T, C);
    for (int i = start + threadIdx.x; i < n; i += blockDim.x) {
        float x = in[i];
        int b = 0;
        #pragma unroll
        for (int j = 0; j < 7; j++) b += (x > th[j]);
        out[i] = __fmaf_rn(T[b], x, C[b]);
    }
}

extern "C" void kernel_launch(void* const* d_in, const int* in_sizes, int n_in,
                              void* d_out, int out_size) {
    const float* logits      = (const float*)d_in[0];
    const float* temperature = (const float*)d_in[1];
    const float* thresholds  = (const float*)d_in[2];
    float* out = (float*)d_out;

    int n  = out_size;           // 8,192,000
    int n4 = n >> 2;             // 2,048,000 float4s

    int grid = (n4 + 1023) / 1024;   // 4 float4 per thread -> 2000 blocks
    if (grid < 1) grid = 1;

    ts_kernel<<<grid, 256>>>((const float4*)logits, (float4*)out,
                             temperature, thresholds, n4);

    int rem = n - (n4 << 2);
    if (rem > 0) {
        ts_tail_kernel<<<1, 256>>>(logits, out, temperature, thresholds, n4 << 2, n);
    }
}

// round 7
// speedup vs baseline: 1.0301x; 1.0301x over previous
#include <cuda_runtime.h>

// TemperatureScaler: piecewise-linear temperature scaling of logits.
// out = T[b]*x + C[b],  b = searchsorted(sorted_thr, x, 'left').
// Launch shape: 1000 blocks x 256 thr x 8 float4 = 2,048,000 float4 exact cover,
// single wave (capacity 8 CTAs/SM x 148 SM = 1184 > 1000).

#define TS_TEMP_MIN 1e-4f

__device__ __forceinline__ void ts_build_params(
    const float* __restrict__ temperature, const float* __restrict__ thresholds,
    float* th /*7 sorted*/, float* T /*8*/, float* C /*8*/)
{
    #pragma unroll
    for (int i = 0; i < 7; i++) th[i] = thresholds[i];
    // insertion sort (7 elements) == jnp.sort
    #pragma unroll
    for (int i = 1; i < 7; i++) {
        float v = th[i];
        int j = i - 1;
        while (j >= 0 && th[j] > v) { th[j + 1] = th[j]; j--; }
        th[j + 1] = v;
    }
    #pragma unroll
    for (int i = 0; i < 8; i++) {
        float t = temperature[i];
        T[i] = t < TS_TEMP_MIN ? TS_TEMP_MIN : t;   // clip(lo=1e-4)
    }
    float thrp[8];
    thrp[0] = 0.0f;
    #pragma unroll
    for (int i = 0; i < 7; i++) thrp[i + 1] = th[i];
    // c = cumsum(diff(pad(thr, left0)) * T[:-1])
    float c[8];
    c[0] = 0.0f;
    #pragma unroll
    for (int i = 0; i < 7; i++) {
        float d = __fadd_rn(thrp[i + 1], -thrp[i]);
        c[i + 1] = __fadd_rn(c[i], __fmul_rn(d, T[i]));
    }
    // C[b] = c[b] - T[b]*thrp[b]  (single-FFMA form; ulp-level deviation only)
    #pragma unroll
    for (int i = 0; i < 8; i++) C[i] = __fmaf_rn(-T[i], thrp[i], c[i]);
}

__global__ __launch_bounds__(256, 7) void ts_kernel(
    const float4* __restrict__ in, float4* __restrict__ out,
    const float* __restrict__ temperature, const float* __restrict__ thresholds,
    int n4)
{
    __shared__ float2 lut[8];   // (T, C)
    __shared__ float sthr[7];   // sorted thresholds

    if (threadIdx.x == 0) {
        float th[7], T[8], C[8];
        ts_build_params(temperature, thresholds, th, T, C);
        #pragma unroll
        for (int i = 0; i < 8; i++) lut[i] = make_float2(T[i], C[i]);
        #pragma unroll
        for (int i = 0; i < 7; i++) sthr[i] = th[i];
    }
    __syncthreads();

    const float t0 = sthr[0], t1 = sthr[1], t2 = sthr[2], t3 = sthr[3],
                t4 = sthr[4], t5 = sthr[5], t6 = sthr[6];

    auto piece = [&](float x) -> float {
        // count of thr_j < x  (side='left': equality -> lower bin)
        int b = (x > t0);
        b += (x > t1); b += (x > t2); b += (x > t3);
        b += (x > t4); b += (x > t5); b += (x > t6);
        float2 L = lut[b];                     // LDS.64, conflict-free
        return __fmaf_rn(L.x, x, L.y);         // one FFMA
    };

    const int base = blockIdx.x * 2048 + threadIdx.x;

    if (base + 1792 < n4) {
        // exact-cover fast path: two MLP-4 batches, no guards
        {
            float4 v0 = in[base];
            float4 v1 = in[base + 256];
            float4 v2 = in[base + 512];
            float4 v3 = in[base + 768];
            float4 r0, r1, r2, r3;
            r0.x = piece(v0.x); r0.y = piece(v0.y); r0.z = piece(v0.z); r0.w = piece(v0.w);
            r1.x = piece(v1.x); r1.y = piece(v1.y); r1.z = piece(v1.z); r1.w = piece(v1.w);
            r2.x = piece(v2.x); r2.y = piece(v2.y); r2.z = piece(v2.z); r2.w = piece(v2.w);
            r3.x = piece(v3.x); r3.y = piece(v3.y); r3.z = piece(v3.z); r3.w = piece(v3.w);
            out[base]       = r0;
            out[base + 256] = r1;
            out[base + 512] = r2;
            out[base + 768] = r3;
        }
        {
            float4 v0 = in[base + 1024];
            float4 v1 = in[base + 1280];
            float4 v2 = in[base + 1536];
            float4 v3 = in[base + 1792];
            float4 r0, r1, r2, r3;
            r0.x = piece(v0.x); r0.y = piece(v0.y); r0.z = piece(v0.z); r0.w = piece(v0.w);
            r1.x = piece(v1.x); r1.y = piece(v1.y); r1.z = piece(v1.z); r1.w = piece(v1.w);
            r2.x = piece(v2.x); r2.y = piece(v2.y); r2.z = piece(v2.z); r2.w = piece(v2.w);
            r3.x = piece(v3.x); r3.y = piece(v3.y); r3.z = piece(v3.z); r3.w = piece(v3.w);
            out[base + 1024] = r0;
            out[base + 1280] = r1;
            out[base + 1536] = r2;
            out[base + 1792] = r3;
        }
    } else {
        #pragma unroll
        for (int k = 0; k < 8; k++) {
            int i = base + k * 256;
            if (i < n4) {
                float4 v = in[i];
                float4 r;
                r.x = piece(v.x); r.y = piece(v.y); r.z = piece(v.z); r.w = piece(v.w);
                out[i] = r;
            }
        }
    }
}

// Scalar tail for out_size % 4 != 0 (not hit for B=64, V=128000)
__global__ void ts_tail_kernel(
    const float* __restrict__ in, float* __restrict__ out,
    const float* __restrict__ temperature, const float* __restrict__ thresholds,
    int start, int n)
{
    float th[7], T[8], C[8];
    ts_build_params(temperature, thresholds, th, T, C);
    for (int i = start + threadIdx.x; i < n; i += blockDim.x) {
        float x = in[i];
        int b = 0;
        #pragma unroll
        for (int j = 0; j < 7; j++) b += (x > th[j]);
        out[i] = __fmaf_rn(T[b], x, C[b]);
    }
}

extern "C" void kernel_launch(void* const* d_in, const int* in_sizes, int n_in,
                              void* d_out, int out_size) {
    const float* logits      = (const float*)d_in[0];
    const float* temperature = (const float*)d_in[1];
    const float* thresholds  = (const float*)d_in[2];
    float* out = (float*)d_out;

    int n  = out_size;           // 8,192,000
    int n4 = n >> 2;             // 2,048,000 float4s

    int grid = (n4 + 2047) / 2048;   // 8 float4 per thread -> 1000 blocks (single wave)
    if (grid < 1) grid = 1;

    ts_kernel<<<grid, 256>>>((const float4*)logits, (float4*)out,
                             temperature, thresholds, n4);

    int rem = n - (n4 << 2);
    if (rem > 0) {
        ts_tail_kernel<<<1, 256>>>(logits, out, temperature, thresholds, n4 << 2, n);
    }
}

// round 8
// speedup vs baseline: 1.0593x; 1.0284x over previous
#include <cuda_runtime.h>

// TemperatureScaler: piecewise-linear temperature scaling of logits.
// out = T[b]*x + C[b],  b = searchsorted(sorted_thr, x, 'left').
// Fast path (uniform grid): magic-number rounding, all fma/alu-pipe ops:
//   y1 = clamp(fma(x, inv, 0.5 - a*inv), 0, 7); y = y1 + 2^23*1.5;
//   b  = float_bits(y) & 7.

#define TS_TEMP_MIN 1e-4f
#define TS_MAGIC    12582912.0f   // 2^23 + 2^22: ulp = 1 -> fp add rounds to int

__device__ __forceinline__ void ts_build_params(
    const float* __restrict__ temperature, const float* __restrict__ thresholds,
    float* th /*7 sorted*/, float* T /*8*/, float* C /*8*/)
{
    #pragma unroll
    for (int i = 0; i < 7; i++) th[i] = thresholds[i];
    // insertion sort (7 elements) == jnp.sort
    #pragma unroll
    for (int i = 1; i < 7; i++) {
        float v = th[i];
        int j = i - 1;
        while (j >= 0 && th[j] > v) { th[j + 1] = th[j]; j--; }
        th[j + 1] = v;
    }
    #pragma unroll
    for (int i = 0; i < 8; i++) {
        float t = temperature[i];
        T[i] = t < TS_TEMP_MIN ? TS_TEMP_MIN : t;   // clip(lo=1e-4)
    }
    float thrp[8];
    thrp[0] = 0.0f;
    #pragma unroll
    for (int i = 0; i < 7; i++) thrp[i + 1] = th[i];
    // c = cumsum(diff(pad(thr, left0)) * T[:-1])
    float c[8];
    c[0] = 0.0f;
    #pragma unroll
    for (int i = 0; i < 7; i++) {
        float d = __fadd_rn(thrp[i + 1], -thrp[i]);
        c[i + 1] = __fadd_rn(c[i], __fmul_rn(d, T[i]));
    }
    // C[b] = c[b] - T[b]*thrp[b]  (single-FFMA form; ulp-level deviation only)
    #pragma unroll
    for (int i = 0; i < 8; i++) C[i] = __fmaf_rn(-T[i], thrp[i], c[i]);
}

__global__ __launch_bounds__(256, 7) void ts_kernel(
    const float4* __restrict__ in, float4* __restrict__ out,
    const float* __restrict__ temperature, const float* __restrict__ thresholds,
    int n4)
{
    __shared__ float2 lut[8];   // (T, C)
    __shared__ float sthr[7];   // sorted thresholds (fallback)
    __shared__ float s_inv, s_f;
    __shared__ int   s_uniform;

    if (threadIdx.x == 0) {
        float th[7], T[8], C[8];
        ts_build_params(temperature, thresholds, th, T, C);
        #pragma unroll
        for (int i = 0; i < 8; i++) lut[i] = make_float2(T[i], C[i]);
        #pragma unroll
        for (int i = 0; i < 7; i++) sthr[i] = th[i];

        // near-uniform grid detection: th[i] ~ th0 + i*s with s = span/6
        float span = __fadd_rn(th[6], -th[0]);
        float s    = __fmul_rn(span, 1.0f / 6.0f);
        int uni = (s > 0.0f);
        float tol = 1e-5f * (fabsf(span) + 1.0f);
        #pragma unroll
        for (int i = 0; i < 7; i++) {
            float ideal = __fmaf_rn((float)i, s, th[0]);
            if (fabsf(th[i] - ideal) > tol) uni = 0;
        }
        float inv = uni ? (1.0f / s) : 0.0f;
        s_inv = inv;
        // f = 0.5 - th0*inv  (kept small & separate so the +MAGIC add does the rounding)
        s_f   = __fmaf_rn(-th[0], inv, 0.5f);
        s_uniform = uni;
    }
    __syncthreads();

    const int base = blockIdx.x * 2048 + threadIdx.x;

    if (s_uniform) {
        const float inv = s_inv, f = s_f;
        auto piece = [&](float x) -> float {
            float y1 = __fmaf_rn(x, inv, f);          // (x-a)/s + 0.5
            y1 = fmaxf(y1, 0.0f);                     // clamp low  (NaN -> 0)
            y1 = fminf(y1, 7.0f);                     // clamp high
            float y  = __fadd_rn(y1, TS_MAGIC);       // round-to-nearest int in mantissa
            int b = __float_as_int(y) & 7;            // bin
            float2 L = lut[b];                        // LDS.64, conflict-free
            return __fmaf_rn(L.x, x, L.y);
        };
        if (base + 1792 < n4) {
            #pragma unroll
            for (int half = 0; half < 2; half++) {
                const int o = base + half * 1024;
                float4 v0 = in[o];
                float4 v1 = in[o + 256];
                float4 v2 = in[o + 512];
                float4 v3 = in[o + 768];
                float4 r0, r1, r2, r3;
                r0.x = piece(v0.x); r0.y = piece(v0.y); r0.z = piece(v0.z); r0.w = piece(v0.w);
                r1.x = piece(v1.x); r1.y = piece(v1.y); r1.z = piece(v1.z); r1.w = piece(v1.w);
                r2.x = piece(v2.x); r2.y = piece(v2.y); r2.z = piece(v2.z); r2.w = piece(v2.w);
                r3.x = piece(v3.x); r3.y = piece(v3.y); r3.z = piece(v3.z); r3.w = piece(v3.w);
                out[o]       = r0;
                out[o + 256] = r1;
                out[o + 512] = r2;
                out[o + 768] = r3;
            }
        } else {
            #pragma unroll
            for (int k = 0; k < 8; k++) {
                int i = base + k * 256;
                if (i < n4) {
                    float4 v = in[i];
                    float4 r;
                    r.x = piece(v.x); r.y = piece(v.y); r.z = piece(v.z); r.w = piece(v.w);
                    out[i] = r;
                }
            }
        }
    } else {
        // generic fallback: compare-chain bin search
        const float t0 = sthr[0], t1 = sthr[1], t2 = sthr[2], t3 = sthr[3],
                    t4 = sthr[4], t5 = sthr[5], t6 = sthr[6];
        auto piece = [&](float x) -> float {
            int b = (x > t0);
            b += (x > t1); b += (x > t2); b += (x > t3);
            b += (x > t4); b += (x > t5); b += (x > t6);
            float2 L = lut[b];
            return __fmaf_rn(L.x, x, L.y);
        };
        #pragma unroll
        for (int k = 0; k < 8; k++) {
            int i = base + k * 256;
            if (i < n4) {
                float4 v = in[i];
                float4 r;
                r.x = piece(v.x); r.y = piece(v.y); r.z = piece(v.z); r.w = piece(v.w);
                out[i] = r;
            }
        }
    }
}

// Scalar tail for out_size % 4 != 0 (not hit for B=64, V=128000)
__global__ void ts_tail_kernel(
    const float* __restrict__ in, float* __restrict__ out,
    const float* __restrict__ temperature, const float* __restrict__ thresholds,
    int start, int n)
{
    float th[7], T[8], C[8];
    ts_build_params(temperature, thresholds, th, T, C);
    for (int i = start + threadIdx.x; i < n; i += blockDim.x) {
        float x = in[i];
        int b = 0;
        #pragma unroll
        for (int j = 0; j < 7; j++) b += (x > th[j]);
        out[i] = __fmaf_rn(T[b], x, C[b]);
    }
}

extern "C" void kernel_launch(void* const* d_in, const int* in_sizes, int n_in,
                              void* d_out, int out_size) {
    const float* logits      = (const float*)d_in[0];
    const float* temperature = (const float*)d_in[1];
    const float* thresholds  = (const float*)d_in[2];
    float* out = (float*)d_out;

    int n  = out_size;           // 8,192,000
    int n4 = n >> 2;             // 2,048,000 float4s

    int grid = (n4 + 2047) / 2048;   // 8 float4 per thread -> 1000 blocks (single wave)
    if (grid < 1) grid = 1;

    ts_kernel<<<grid, 256>>>((const float4*)logits, (float4*)out,
                             temperature, thresholds, n4);

    int rem = n - (n4 << 2);
    if (rem > 0) {
        ts_tail_kernel<<<1, 256>>>(logits, out, temperature, thresholds, n4 << 2, n);
    }
}